// round 10
// baseline (speedup 1.0000x reference)
#include <cuda_runtime.h>
#include <cuda_bf16.h>

#define NN      65536
#define NE      1048576
#define NG      64
#define NPG     1024
#define CF      32
#define PADF    34      // floats per smem row: 136B, 8B-aligned, spans all banks
#define RSTRIDE 64      // edge slots per node

typedef unsigned long long ull;

__device__ int   g_deg[NN];
__device__ int   g_cnt[NN];
__device__ int   g_cur[NN];
// interleaved per node-PAIR: [(node/2)][slot][node%2]; zero-init
__device__ int2  g_edges[(size_t)NN * RSTRIDE];
__device__ float g_tx[640ull * NN];
__device__ float g_ha[(size_t)NN * 64];
__device__ float g_hb[(size_t)NN * 64];

__device__ __forceinline__ ull pack2(float x, float y) {
    ull r; asm("mov.b64 %0, {%1, %2};" : "=l"(r) : "f"(x), "f"(y)); return r;
}
__device__ __forceinline__ void ffma2(ull& d, ull a, ull b) {
    asm("fma.rn.f32x2 %0, %1, %2, %0;" : "+l"(d) : "l"(a), "l"(b));
}
__device__ __forceinline__ void unpack2(ull v, float& x, float& y) {
    asm("mov.b64 {%0, %1}, %2;" : "=f"(x), "=f"(y) : "l"(v));
}

// ---------------- prep ----------------
__global__ void zero_kernel() {
    int i = blockIdx.x * blockDim.x + threadIdx.x;
    if (i < NN) { g_deg[i] = 0; g_cnt[i] = 0; g_cur[i] = 0; }
}

__global__ void deg_kernel(const int* __restrict__ ei) {
    int e = blockIdx.x * blockDim.x + threadIdx.x;
    if (e >= NE) return;
    int s = ei[e], d = ei[NE + e];
    if (s != d) { atomicAdd(&g_deg[s], 1); atomicAdd(&g_cnt[d], 1); }
}

__global__ void fill_kernel(const int* __restrict__ ei,
                            const float* __restrict__ lam) {
    int e = blockIdx.x * blockDim.x + threadIdx.x;
    if (e >= NE) return;
    int s = ei[e], d = ei[NE + e];
    if (s == d) return;
    int od = g_deg[d];
    float dd = (od > 0) ? rsqrtf((float)od) : 0.0f;
    float w = -2.0f * rsqrtf((float)g_deg[s]) * dd / lam[s >> 10];
    int slot = atomicAdd(&g_cur[d], 1);
    int sloc = s & (NPG - 1);
    size_t idx = ((size_t)(d >> 1) * RSTRIDE + slot) * 2 + (d & 1);
    // smem row BYTE offset of src, pre-scaled
    g_edges[idx] = make_int2(sloc * (PADF * 4), __float_as_int(w));
}

// ---------------- Chebyshev recurrence ----------------
// CTA = (32-feature chunk, graph), 1024 threads, 1 CTA/SM, SINGLE smem buffer.
// Warp iter: 2 nodes (sub=lane>>4), 16 feature-pairs (fp=lane&15). Rows are
// 136B -> every gather access spans all 32 banks -> fixed 2-way (100% xbar).
// Phase A: acc in regs for 16 node-pairs. Phase B: in-place update of own row
// (Tx_{k-2} own values re-read from txout global). Then coalesced writeout.
template<int F>
__global__ void __launch_bounds__(1024, 1)
spmv_kernel(const float* __restrict__ hin, const float* __restrict__ lam,
            float* __restrict__ txout) {
    extern __shared__ float sm[];   // [1024][PADF]

    const int g = blockIdx.y, cb = blockIdx.x * CF, t = threadIdx.x;
    const int gbase = g * NPG;
    const float diag = 2.0f / lam[g] - 1.0f;

    // load chunk (coalesced LDG, conflict-free STS)
    #pragma unroll
    for (int r = 0; r < CF; r++) {
        int i = r * 1024 + t;
        int row = i >> 5, f = i & 31;
        sm[row * PADF + f] = hin[(size_t)(gbase + row) * F + cb + f];
    }
    __syncthreads();

    // Tx0 -> transposed global (row-read 2-way at worst, STG coalesced)
    #pragma unroll
    for (int f = 0; f < CF; f++)
        txout[(size_t)(cb + f) * NN + gbase + t] = sm[t * PADF + f];

    const int lane = t & 31, warp = t >> 5;
    const int fp = lane & 15, sub = lane >> 4;
    const int fpb = fp * 8;
    int mydeg = g_cnt[gbase + warp * 32 + lane];
    int pmax = max(mydeg, __shfl_xor_sync(0xffffffffu, mydeg, 1)); // per node-pair

    const char* smb = (const char*)sm;
    char* smw = (char*)sm;
    const size_t npg0 = (size_t)((gbase + warp * 32) >> 1) * (RSTRIDE * 2);

    for (int k = 1; k < 5; k++) {
        float ax[16], ay[16];
        // ---- phase A: gather (reads only) ----
        #pragma unroll
        for (int p = 0; p < 16; p++) {
            const int gdeg = __shfl_sync(0xffffffffu, pmax, 2 * p);
            const int2* ebase = g_edges + npg0 + p * (RSTRIDE * 2) + sub;
            float x0 = 0.0f, y0 = 0.0f;
            #pragma unroll 1
            for (int i = 0; i < gdeg; i += 2) {
                int2 e0 = ebase[2 * i];
                int2 e1 = ebase[2 * i + 2];
                float2 v0 = *(const float2*)(smb + e0.x + fpb);
                float2 v1 = *(const float2*)(smb + e1.x + fpb);
                float w0 = __int_as_float(e0.y), w1 = __int_as_float(e1.y);
                x0 = fmaf(w0, v0.x, x0); y0 = fmaf(w0, v0.y, y0);
                x0 = fmaf(w1, v1.x, x0); y0 = fmaf(w1, v1.y, y0);
            }
            ax[p] = x0; ay[p] = y0;
        }
        __syncthreads();
        // ---- phase B: in-place update (own row only) ----
        #pragma unroll
        for (int p = 0; p < 16; p++) {
            const int node = warp * 32 + 2 * p + sub;
            float2* own = (float2*)(smw + node * (PADF * 4) + fpb);
            float2 c = *own;
            float lx = fmaf(diag, c.x, ax[p]);
            float ly = fmaf(diag, c.y, ay[p]);
            if (k > 1) {
                const float* pv = txout +
                    (size_t)((k - 2) * F + cb + 2 * fp) * NN + gbase + node;
                lx = 2.0f * lx - pv[0];
                ly = 2.0f * ly - pv[NN];
            }
            *own = make_float2(lx, ly);
        }
        __syncthreads();
        // ---- writeout Tx_k ----
        #pragma unroll
        for (int f = 0; f < CF; f++)
            txout[(size_t)(k * F + cb + f) * NN + gbase + t] = sm[t * PADF + f];
    }
}

// ---------------- GEMM: out = relu(A^T W + b), A:[K][NN], W:[K][N] ----------------
template<int K, int N, int MT>
__global__ void __launch_bounds__(256)
gemm_kernel(const float* __restrict__ A, const float* __restrict__ W,
            const float* __restrict__ bias, float* __restrict__ out) {
    constexpr int NJG = N / 8;
    constexpr int MG  = MT / 8;
    static_assert(MG * NJG == 256, "cfg");
    __shared__ __align__(16) float As[16 * MT];
    __shared__ __align__(16) float Ws[16 * N];

    const int t = threadIdx.x;
    const int jg = t % NJG, mg = t / NJG;
    const int m0 = blockIdx.x * MT;

    ull acc[8][4];
    #pragma unroll
    for (int a = 0; a < 8; a++)
        #pragma unroll
        for (int b = 0; b < 4; b++) acc[a][b] = 0ULL;

    for (int k0 = 0; k0 < K; k0 += 16) {
        for (int i = t; i < 16 * MT; i += 256)
            As[i] = A[(size_t)(k0 + i / MT) * NN + m0 + (i % MT)];
        for (int i = t; i < 16 * N; i += 256)
            Ws[i] = W[k0 * N + i];
        __syncthreads();
        #pragma unroll
        for (int kk = 0; kk < 16; kk++) {
            const float* ar = &As[kk * MT + mg];
            const ull* wr = (const ull*)&Ws[kk * N + jg * 8];
            ull w0 = wr[0], w1 = wr[1], w2 = wr[2], w3 = wr[3];
            #pragma unroll
            for (int tt = 0; tt < 8; tt++) {
                float a = ar[tt * MG];
                ull ab = pack2(a, a);
                ffma2(acc[tt][0], ab, w0);
                ffma2(acc[tt][1], ab, w1);
                ffma2(acc[tt][2], ab, w2);
                ffma2(acc[tt][3], ab, w3);
            }
        }
        __syncthreads();
    }

    #pragma unroll
    for (int tt = 0; tt < 8; tt++) {
        size_t node = m0 + mg + tt * MG;
        #pragma unroll
        for (int p = 0; p < 4; p++) {
            float x, y; unpack2(acc[tt][p], x, y);
            int j = jg * 8 + 2 * p;
            x = fmaxf(x + bias[j], 0.0f);
            y = fmaxf(y + bias[j + 1], 0.0f);
            *reinterpret_cast<float2*>(&out[node * N + j]) = make_float2(x, y);
        }
    }
}

// ---------------- pool + FC ----------------
__global__ void pool_fc_kernel(const float* __restrict__ h,
                               const float* __restrict__ fcW1, const float* __restrict__ fcb1,
                               const float* __restrict__ fcW2, const float* __restrict__ fcb2,
                               float* __restrict__ out) {
    __shared__ float red[256];
    __shared__ float pool[64];
    __shared__ float z1[10];
    int g = blockIdx.x, t = threadIdx.x;
    int f = t & 63, part = t >> 6;
    float s = 0.0f;
    for (int n = part; n < NPG; n += 4)
        s += h[(size_t)(g * NPG + n) * 64 + f];
    red[t] = s;
    __syncthreads();
    if (part == 0)
        pool[f] = (red[f] + red[64 + f] + red[128 + f] + red[192 + f]) * (1.0f / NPG);
    __syncthreads();
    if (t < 10) {
        float z = fcb1[t];
        for (int i = 0; i < 64; i++) z += pool[i] * fcW1[i * 10 + t];
        z1[t] = fmaxf(z, 0.0f);
    }
    __syncthreads();
    if (t < 10) {
        float z = fcb2[t];
        for (int j = 0; j < 10; j++) z += z1[j] * fcW2[j * 10 + t];
        out[g * 10 + t] = z;
    }
}

// ---------------- launch ----------------
extern "C" void kernel_launch(void* const* d_in, const int* in_sizes, int n_in,
                              void* d_out, int out_size) {
    const float* x     = (const float*)d_in[0];
    const int*   ei    = (const int*)d_in[1];
    const float* lam   = (const float*)d_in[3];
    const float* W1 = (const float*)d_in[4];  const float* b1 = (const float*)d_in[5];
    const float* W2 = (const float*)d_in[6];  const float* b2 = (const float*)d_in[7];
    const float* W3 = (const float*)d_in[8];  const float* b3 = (const float*)d_in[9];
    const float* fcW1 = (const float*)d_in[10]; const float* fcb1 = (const float*)d_in[11];
    const float* fcW2 = (const float*)d_in[12]; const float* fcb2 = (const float*)d_in[13];
    float* out = (float*)d_out;

    const int SMEM = NPG * PADF * sizeof(float);  // 139264
    cudaFuncSetAttribute(spmv_kernel<128>, cudaFuncAttributeMaxDynamicSharedMemorySize, SMEM);
    cudaFuncSetAttribute(spmv_kernel<32>,  cudaFuncAttributeMaxDynamicSharedMemorySize, SMEM);
    cudaFuncSetAttribute(spmv_kernel<64>,  cudaFuncAttributeMaxDynamicSharedMemorySize, SMEM);

    float* tx = nullptr; float* ha = nullptr; float* hb = nullptr;
    cudaGetSymbolAddress((void**)&tx, g_tx);
    cudaGetSymbolAddress((void**)&ha, g_ha);
    cudaGetSymbolAddress((void**)&hb, g_hb);

    zero_kernel<<<NN / 256, 256>>>();                       // 0
    deg_kernel<<<NE / 256, 256>>>(ei);                      // 1
    fill_kernel<<<NE / 256, 256>>>(ei, lam);                // 2

    spmv_kernel<128><<<dim3(4, NG), 1024, SMEM>>>(x, lam, tx);    // 3 <- ncu captures this
    gemm_kernel<640, 32, 512><<<NN / 512, 256>>>(tx, W1, b1, ha);

    spmv_kernel<32><<<dim3(1, NG), 1024, SMEM>>>(ha, lam, tx);
    gemm_kernel<160, 64, 256><<<NN / 256, 256>>>(tx, W2, b2, hb);

    spmv_kernel<64><<<dim3(2, NG), 1024, SMEM>>>(hb, lam, tx);
    gemm_kernel<320, 64, 256><<<NN / 256, 256>>>(tx, W3, b3, ha);

    pool_fc_kernel<<<NG, 256>>>(ha, fcW1, fcb1, fcW2, fcb2, out);
}

// round 11
// speedup vs baseline: 1.2300x; 1.2300x over previous
#include <cuda_runtime.h>
#include <cuda_bf16.h>

#define NN      65536
#define NE      1048576
#define NG      64
#define NPG     1024
#define CF      8
#define RSTRIDE 64      // edge slots per node

typedef unsigned long long ull;

__device__ int   g_deg[NN];
__device__ int   g_cnt[NN];
__device__ int   g_cur[NN];
// interleave: [(node/8)][slot/2][node%8][slot%2] -> per sub-lane, slot pair = 16B
__device__ __align__(16) int2 g_edges[(size_t)NN * RSTRIDE];
__device__ float g_tx[640ull * NN];
__device__ float g_ha[(size_t)NN * 64];
__device__ float g_hb[(size_t)NN * 64];

__device__ __forceinline__ ull pack2(float x, float y) {
    ull r; asm("mov.b64 %0, {%1, %2};" : "=l"(r) : "f"(x), "f"(y)); return r;
}
__device__ __forceinline__ void ffma2(ull& d, ull a, ull b) {
    asm("fma.rn.f32x2 %0, %1, %2, %0;" : "+l"(d) : "l"(a), "l"(b));
}
__device__ __forceinline__ void unpack2(ull v, float& x, float& y) {
    asm("mov.b64 {%0, %1}, %2;" : "=f"(x), "=f"(y) : "l"(v));
}

// ---------------- prep ----------------
__global__ void zero_kernel() {
    int i = blockIdx.x * blockDim.x + threadIdx.x;
    if (i < NN) { g_deg[i] = 0; g_cnt[i] = 0; g_cur[i] = 0; }
}

__global__ void deg_kernel(const int* __restrict__ ei) {
    int e = blockIdx.x * blockDim.x + threadIdx.x;
    if (e >= NE) return;
    int s = ei[e], d = ei[NE + e];
    if (s != d) { atomicAdd(&g_deg[s], 1); atomicAdd(&g_cnt[d], 1); }
}

__global__ void fill_kernel(const int* __restrict__ ei,
                            const float* __restrict__ lam) {
    int e = blockIdx.x * blockDim.x + threadIdx.x;
    if (e >= NE) return;
    int s = ei[e], d = ei[NE + e];
    if (s == d) return;
    int od = g_deg[d];
    float dd = (od > 0) ? rsqrtf((float)od) : 0.0f;
    float w = -2.0f * rsqrtf((float)g_deg[s]) * dd / lam[s >> 10];
    int slot = atomicAdd(&g_cur[d], 1);
    int sloc = s & (NPG - 1);
    // smem byte offset of src row with swizzle class baked in (bits 3-4)
    int eoff = (sloc << 5) | (((sloc >> 2) & 3) << 3);
    size_t idx = (size_t)(d & ~7) * RSTRIDE
               + (size_t)(slot >> 1) * 16 + (d & 7) * 2 + (slot & 1);
    g_edges[idx] = make_int2(eoff, __float_as_int(w));
}

// ---------------- Chebyshev recurrence ----------------
// CTA = (8-feature chunk, graph), 1024 threads, 2 CTAs/SM (64KB smem).
// Warp iter: 8 nodes (sub=lane>>2), feature pair fp=lane&3 (float2).
// No cross-lane reduction; all 32 lanes write back directly.
// Edge fetch: one LDG.128 = 2 edges per sub (slot-pair interleave); x2 in flight.
template<int F>
__global__ void __launch_bounds__(1024, 2)
spmv_kernel(const float* __restrict__ hin, const float* __restrict__ lam,
            float* __restrict__ txout) {
    extern __shared__ float sm[];
    float* buf0 = sm;                   // [1024][8] swizzled
    float* buf1 = sm + NPG * 8;

    const int g = blockIdx.y, cb = blockIdx.x * CF, t = threadIdx.x;
    const int gbase = g * NPG;
    const float diag = 2.0f / lam[g] - 1.0f;

    // load chunk -> swizzled smem
    const float* hp = hin + (size_t)gbase * F + cb;
    #pragma unroll
    for (int r = 0; r < CF; r++) {
        int i = r * 1024 + t;
        int row = i >> 3, f = i & 7;
        int sw = ((f >> 1) ^ ((row >> 2) & 3)) * 2 + (f & 1);
        buf0[row * 8 + sw] = hp[row * F + f];
    }
    __syncthreads();

    // Tx0 -> transposed global
    {
        int s_t = (t >> 2) & 3;
        #pragma unroll
        for (int f = 0; f < CF; f++) {
            int sw = ((f >> 1) ^ s_t) * 2 + (f & 1);
            txout[(size_t)(cb + f) * NN + gbase + t] = buf0[t * 8 + sw];
        }
    }

    const int lane = t & 31, warp = t >> 5;
    const int fp8 = (lane & 3) * 8;
    const int sub = lane >> 2;
    int v = g_cnt[gbase + warp * 32 + lane];
    v = max(v, __shfl_xor_sync(0xffffffffu, v, 1));
    v = max(v, __shfl_xor_sync(0xffffffffu, v, 2));
    v = max(v, __shfl_xor_sync(0xffffffffu, v, 4));   // max deg per 8-lane group

    float* cur = buf0; float* oth = buf1;
    for (int k = 1; k < 5; k++) {
        const char* curb = (const char*)cur;
        #pragma unroll 1
        for (int p = 0; p < 4; p++) {
            const int gdeg = __shfl_sync(0xffffffffu, v, p * 8);
            const int node8 = warp * 32 + p * 8;
            const char* ebase =
                (const char*)(g_edges + (size_t)(gbase + node8) * RSTRIDE) + sub * 16;
            float ax = 0.0f, ay = 0.0f;
            #pragma unroll 1
            for (int i = 0; i < gdeg; i += 4) {
                int4 E0 = *(const int4*)(ebase + (size_t)i * 64);
                int4 E1 = *(const int4*)(ebase + (size_t)i * 64 + 128);
                float2 v0 = *(const float2*)(curb + (E0.x ^ fp8));
                float2 v1 = *(const float2*)(curb + (E0.z ^ fp8));
                float2 v2 = *(const float2*)(curb + (E1.x ^ fp8));
                float2 v3 = *(const float2*)(curb + (E1.z ^ fp8));
                float w0 = __int_as_float(E0.y), w1 = __int_as_float(E0.w);
                float w2 = __int_as_float(E1.y), w3 = __int_as_float(E1.w);
                ax = fmaf(w0, v0.x, ax); ay = fmaf(w0, v0.y, ay);
                ax = fmaf(w1, v1.x, ax); ay = fmaf(w1, v1.y, ay);
                ax = fmaf(w2, v2.x, ax); ay = fmaf(w2, v2.y, ay);
                ax = fmaf(w3, v3.x, ax); ay = fmaf(w3, v3.y, ay);
            }
            const int dloc = node8 + sub;
            const int swb = fp8 ^ (((dloc >> 2) & 3) << 3);
            float2 c = *(const float2*)((const char*)cur + dloc * 32 + swb);
            float lx = fmaf(diag, c.x, ax);
            float ly = fmaf(diag, c.y, ay);
            float2* op = (float2*)((char*)oth + dloc * 32 + swb);
            if (k > 1) { float2 o = *op; lx = 2.0f * lx - o.x; ly = 2.0f * ly - o.y; }
            *op = make_float2(lx, ly);
        }
        __syncthreads();
        int s_t = (t >> 2) & 3;
        #pragma unroll
        for (int f = 0; f < CF; f++) {
            int sw = ((f >> 1) ^ s_t) * 2 + (f & 1);
            txout[(size_t)(k * F + cb + f) * NN + gbase + t] = oth[t * 8 + sw];
        }
        float* tmp = cur; cur = oth; oth = tmp;
        __syncthreads();
    }
}

// ---------------- GEMM: out = relu(A^T W + b), A:[K][NN], W:[K][N] ----------------
template<int K, int N, int MT>
__global__ void __launch_bounds__(256)
gemm_kernel(const float* __restrict__ A, const float* __restrict__ W,
            const float* __restrict__ bias, float* __restrict__ out) {
    constexpr int NJG = N / 8;
    constexpr int MG  = MT / 8;
    static_assert(MG * NJG == 256, "cfg");
    __shared__ __align__(16) float As[16 * MT];
    __shared__ __align__(16) float Ws[16 * N];

    const int t = threadIdx.x;
    const int jg = t % NJG, mg = t / NJG;
    const int m0 = blockIdx.x * MT;

    ull acc[8][4];
    #pragma unroll
    for (int a = 0; a < 8; a++)
        #pragma unroll
        for (int b = 0; b < 4; b++) acc[a][b] = 0ULL;

    for (int k0 = 0; k0 < K; k0 += 16) {
        for (int i = t; i < 16 * MT; i += 256)
            As[i] = A[(size_t)(k0 + i / MT) * NN + m0 + (i % MT)];
        for (int i = t; i < 16 * N; i += 256)
            Ws[i] = W[k0 * N + i];
        __syncthreads();
        #pragma unroll
        for (int kk = 0; kk < 16; kk++) {
            const float* ar = &As[kk * MT + mg];
            const ull* wr = (const ull*)&Ws[kk * N + jg * 8];
            ull w0 = wr[0], w1 = wr[1], w2 = wr[2], w3 = wr[3];
            #pragma unroll
            for (int tt = 0; tt < 8; tt++) {
                float a = ar[tt * MG];
                ull ab = pack2(a, a);
                ffma2(acc[tt][0], ab, w0);
                ffma2(acc[tt][1], ab, w1);
                ffma2(acc[tt][2], ab, w2);
                ffma2(acc[tt][3], ab, w3);
            }
        }
        __syncthreads();
    }

    #pragma unroll
    for (int tt = 0; tt < 8; tt++) {
        size_t node = m0 + mg + tt * MG;
        #pragma unroll
        for (int p = 0; p < 4; p++) {
            float x, y; unpack2(acc[tt][p], x, y);
            int j = jg * 8 + 2 * p;
            x = fmaxf(x + bias[j], 0.0f);
            y = fmaxf(y + bias[j + 1], 0.0f);
            *reinterpret_cast<float2*>(&out[node * N + j]) = make_float2(x, y);
        }
    }
}

// ---------------- pool + FC ----------------
__global__ void pool_fc_kernel(const float* __restrict__ h,
                               const float* __restrict__ fcW1, const float* __restrict__ fcb1,
                               const float* __restrict__ fcW2, const float* __restrict__ fcb2,
                               float* __restrict__ out) {
    __shared__ float red[256];
    __shared__ float pool[64];
    __shared__ float z1[10];
    int g = blockIdx.x, t = threadIdx.x;
    int f = t & 63, part = t >> 6;
    float s = 0.0f;
    for (int n = part; n < NPG; n += 4)
        s += h[(size_t)(g * NPG + n) * 64 + f];
    red[t] = s;
    __syncthreads();
    if (part == 0)
        pool[f] = (red[f] + red[64 + f] + red[128 + f] + red[192 + f]) * (1.0f / NPG);
    __syncthreads();
    if (t < 10) {
        float z = fcb1[t];
        for (int i = 0; i < 64; i++) z += pool[i] * fcW1[i * 10 + t];
        z1[t] = fmaxf(z, 0.0f);
    }
    __syncthreads();
    if (t < 10) {
        float z = fcb2[t];
        for (int j = 0; j < 10; j++) z += z1[j] * fcW2[j * 10 + t];
        out[g * 10 + t] = z;
    }
}

// ---------------- launch ----------------
extern "C" void kernel_launch(void* const* d_in, const int* in_sizes, int n_in,
                              void* d_out, int out_size) {
    const float* x     = (const float*)d_in[0];
    const int*   ei    = (const int*)d_in[1];
    const float* lam   = (const float*)d_in[3];
    const float* W1 = (const float*)d_in[4];  const float* b1 = (const float*)d_in[5];
    const float* W2 = (const float*)d_in[6];  const float* b2 = (const float*)d_in[7];
    const float* W3 = (const float*)d_in[8];  const float* b3 = (const float*)d_in[9];
    const float* fcW1 = (const float*)d_in[10]; const float* fcb1 = (const float*)d_in[11];
    const float* fcW2 = (const float*)d_in[12]; const float* fcb2 = (const float*)d_in[13];
    float* out = (float*)d_out;

    const int SMEM = 2 * NPG * CF * sizeof(float);  // 65536
    cudaFuncSetAttribute(spmv_kernel<128>, cudaFuncAttributeMaxDynamicSharedMemorySize, SMEM);
    cudaFuncSetAttribute(spmv_kernel<32>,  cudaFuncAttributeMaxDynamicSharedMemorySize, SMEM);
    cudaFuncSetAttribute(spmv_kernel<64>,  cudaFuncAttributeMaxDynamicSharedMemorySize, SMEM);

    float* tx = nullptr; float* ha = nullptr; float* hb = nullptr;
    cudaGetSymbolAddress((void**)&tx, g_tx);
    cudaGetSymbolAddress((void**)&ha, g_ha);
    cudaGetSymbolAddress((void**)&hb, g_hb);

    zero_kernel<<<NN / 256, 256>>>();                       // 0
    deg_kernel<<<NE / 256, 256>>>(ei);                      // 1
    fill_kernel<<<NE / 256, 256>>>(ei, lam);                // 2

    spmv_kernel<128><<<dim3(16, NG), 1024, SMEM>>>(x, lam, tx);   // 3 <- ncu captures this
    gemm_kernel<640, 32, 512><<<NN / 512, 256>>>(tx, W1, b1, ha);

    spmv_kernel<32><<<dim3(4, NG), 1024, SMEM>>>(ha, lam, tx);
    gemm_kernel<160, 64, 256><<<NN / 256, 256>>>(tx, W2, b2, hb);

    spmv_kernel<64><<<dim3(8, NG), 1024, SMEM>>>(hb, lam, tx);
    gemm_kernel<320, 64, 256><<<NN / 256, 256>>>(tx, W3, b3, ha);

    pool_fc_kernel<<<NG, 256>>>(ha, fcW1, fcb1, fcW2, fcb2, out);
}

// round 12
// speedup vs baseline: 1.5929x; 1.2950x over previous
#include <cuda_runtime.h>
#include <cuda_bf16.h>

#define NN      65536
#define NE      1048576
#define NG      64
#define NPG     1024
#define CF      8
#define RSTRIDE 64      // edge slots per node

typedef unsigned long long ull;

__device__ int   g_deg[NN];
__device__ int   g_cnt[NN];
__device__ int   g_cur[NN];
// interleave: [(node/8)][slot/2][node%8][slot%2] -> per sub-lane, slot pair = 16B
__device__ __align__(16) int2 g_edges[(size_t)NN * RSTRIDE];
__device__ float g_tx[640ull * NN];
__device__ float g_ha[(size_t)NN * 64];
__device__ float g_hb[(size_t)NN * 64];

__device__ __forceinline__ ull pack2(float x, float y) {
    ull r; asm("mov.b64 %0, {%1, %2};" : "=l"(r) : "f"(x), "f"(y)); return r;
}
__device__ __forceinline__ void ffma2(ull& d, ull a, ull b) {
    asm("fma.rn.f32x2 %0, %1, %2, %0;" : "+l"(d) : "l"(a), "l"(b));
}
__device__ __forceinline__ void unpack2(ull v, float& x, float& y) {
    asm("mov.b64 {%0, %1}, %2;" : "=f"(x), "=f"(y) : "l"(v));
}

// ---------------- prep ----------------
// Runs at the TAIL of each launch; __device__ arrays are zero-initialized at
// load, so the first call already sees zeros. Each replay re-zeroes for the next.
__global__ void zero_kernel() {
    int i = blockIdx.x * blockDim.x + threadIdx.x;
    if (i < NN) { g_deg[i] = 0; g_cnt[i] = 0; g_cur[i] = 0; }
}

__global__ void deg_kernel(const int* __restrict__ ei) {
    int e = blockIdx.x * blockDim.x + threadIdx.x;
    if (e >= NE) return;
    int s = ei[e], d = ei[NE + e];
    if (s != d) { atomicAdd(&g_deg[s], 1); atomicAdd(&g_cnt[d], 1); }
}

__global__ void fill_kernel(const int* __restrict__ ei,
                            const float* __restrict__ lam) {
    int e = blockIdx.x * blockDim.x + threadIdx.x;
    if (e >= NE) return;
    int s = ei[e], d = ei[NE + e];
    if (s == d) return;
    int od = g_deg[d];
    float dd = (od > 0) ? rsqrtf((float)od) : 0.0f;
    float w = -2.0f * rsqrtf((float)g_deg[s]) * dd / lam[s >> 10];
    int slot = atomicAdd(&g_cur[d], 1);
    int sloc = s & (NPG - 1);
    // smem byte offset of src row with swizzle class baked in (bits 3-4)
    int eoff = (sloc << 5) | (((sloc >> 2) & 3) << 3);
    size_t idx = (size_t)(d & ~7) * RSTRIDE
               + (size_t)(slot >> 1) * 16 + (d & 7) * 2 + (slot & 1);
    g_edges[idx] = make_int2(eoff, __float_as_int(w));
}

// ---------------- Chebyshev recurrence (unchanged from R11) ----------------
template<int F>
__global__ void __launch_bounds__(1024, 2)
spmv_kernel(const float* __restrict__ hin, const float* __restrict__ lam,
            float* __restrict__ txout) {
    extern __shared__ float sm[];
    float* buf0 = sm;                   // [1024][8] swizzled
    float* buf1 = sm + NPG * 8;

    const int g = blockIdx.y, cb = blockIdx.x * CF, t = threadIdx.x;
    const int gbase = g * NPG;
    const float diag = 2.0f / lam[g] - 1.0f;

    const float* hp = hin + (size_t)gbase * F + cb;
    #pragma unroll
    for (int r = 0; r < CF; r++) {
        int i = r * 1024 + t;
        int row = i >> 3, f = i & 7;
        int sw = ((f >> 1) ^ ((row >> 2) & 3)) * 2 + (f & 1);
        buf0[row * 8 + sw] = hp[row * F + f];
    }
    __syncthreads();

    {
        int s_t = (t >> 2) & 3;
        #pragma unroll
        for (int f = 0; f < CF; f++) {
            int sw = ((f >> 1) ^ s_t) * 2 + (f & 1);
            txout[(size_t)(cb + f) * NN + gbase + t] = buf0[t * 8 + sw];
        }
    }

    const int lane = t & 31, warp = t >> 5;
    const int fp8 = (lane & 3) * 8;
    const int sub = lane >> 2;
    int v = g_cnt[gbase + warp * 32 + lane];
    v = max(v, __shfl_xor_sync(0xffffffffu, v, 1));
    v = max(v, __shfl_xor_sync(0xffffffffu, v, 2));
    v = max(v, __shfl_xor_sync(0xffffffffu, v, 4));

    float* cur = buf0; float* oth = buf1;
    for (int k = 1; k < 5; k++) {
        const char* curb = (const char*)cur;
        #pragma unroll 1
        for (int p = 0; p < 4; p++) {
            const int gdeg = __shfl_sync(0xffffffffu, v, p * 8);
            const int node8 = warp * 32 + p * 8;
            const char* ebase =
                (const char*)(g_edges + (size_t)(gbase + node8) * RSTRIDE) + sub * 16;
            float ax = 0.0f, ay = 0.0f;
            #pragma unroll 1
            for (int i = 0; i < gdeg; i += 4) {
                int4 E0 = *(const int4*)(ebase + (size_t)i * 64);
                int4 E1 = *(const int4*)(ebase + (size_t)i * 64 + 128);
                float2 v0 = *(const float2*)(curb + (E0.x ^ fp8));
                float2 v1 = *(const float2*)(curb + (E0.z ^ fp8));
                float2 v2 = *(const float2*)(curb + (E1.x ^ fp8));
                float2 v3 = *(const float2*)(curb + (E1.z ^ fp8));
                float w0 = __int_as_float(E0.y), w1 = __int_as_float(E0.w);
                float w2 = __int_as_float(E1.y), w3 = __int_as_float(E1.w);
                ax = fmaf(w0, v0.x, ax); ay = fmaf(w0, v0.y, ay);
                ax = fmaf(w1, v1.x, ax); ay = fmaf(w1, v1.y, ay);
                ax = fmaf(w2, v2.x, ax); ay = fmaf(w2, v2.y, ay);
                ax = fmaf(w3, v3.x, ax); ay = fmaf(w3, v3.y, ay);
            }
            const int dloc = node8 + sub;
            const int swb = fp8 ^ (((dloc >> 2) & 3) << 3);
            float2 c = *(const float2*)((const char*)cur + dloc * 32 + swb);
            float lx = fmaf(diag, c.x, ax);
            float ly = fmaf(diag, c.y, ay);
            float2* op = (float2*)((char*)oth + dloc * 32 + swb);
            if (k > 1) { float2 o = *op; lx = 2.0f * lx - o.x; ly = 2.0f * ly - o.y; }
            *op = make_float2(lx, ly);
        }
        __syncthreads();
        int s_t = (t >> 2) & 3;
        #pragma unroll
        for (int f = 0; f < CF; f++) {
            int sw = ((f >> 1) ^ s_t) * 2 + (f & 1);
            txout[(size_t)(k * F + cb + f) * NN + gbase + t] = oth[t * 8 + sw];
        }
        float* tmp = cur; cur = oth; oth = tmp;
        __syncthreads();
    }
}

// ---------------- GEMM v2: out = relu(A^T W + b), A:[K][NN], W:[K][N] ----------------
// 256 threads; thread tile = 8 CONTIGUOUS nodes x 8 outs. A fetch: 2 LDS.128/kk.
template<int K, int N, int MT>
__global__ void __launch_bounds__(256, 2)
gemm_kernel(const float* __restrict__ A, const float* __restrict__ W,
            const float* __restrict__ bias, float* __restrict__ out) {
    constexpr int NJG = N / 8;
    constexpr int MG  = MT / 8;
    static_assert(MG * NJG == 256, "cfg");
    __shared__ __align__(16) float As[16 * MT];
    __shared__ __align__(16) float Ws[16 * N];

    const int t = threadIdx.x;
    const int jg = t % NJG, mg = t / NJG;
    const int m0 = blockIdx.x * MT;

    ull acc[8][4];
    #pragma unroll
    for (int a = 0; a < 8; a++)
        #pragma unroll
        for (int b = 0; b < 4; b++) acc[a][b] = 0ULL;

    for (int k0 = 0; k0 < K; k0 += 16) {
        #pragma unroll
        for (int i = t * 4; i < 16 * MT; i += 1024)
            *(float4*)&As[i] =
                *(const float4*)&A[(size_t)(k0 + i / MT) * NN + m0 + (i % MT)];
        for (int i = t * 4; i < 16 * N; i += 1024)
            *(float4*)&Ws[i] = *(const float4*)&W[(size_t)k0 * N + i];
        __syncthreads();
        #pragma unroll
        for (int kk = 0; kk < 16; kk++) {
            const float4* ap = (const float4*)&As[kk * MT + mg * 8];
            float4 a0 = ap[0], a1 = ap[1];
            const ull* wr = (const ull*)&Ws[kk * N + jg * 8];
            ull w0 = wr[0], w1 = wr[1], w2 = wr[2], w3 = wr[3];
            float av[8] = {a0.x, a0.y, a0.z, a0.w, a1.x, a1.y, a1.z, a1.w};
            #pragma unroll
            for (int tt = 0; tt < 8; tt++) {
                ull ab = pack2(av[tt], av[tt]);
                ffma2(acc[tt][0], ab, w0);
                ffma2(acc[tt][1], ab, w1);
                ffma2(acc[tt][2], ab, w2);
                ffma2(acc[tt][3], ab, w3);
            }
        }
        __syncthreads();
    }

    #pragma unroll
    for (int tt = 0; tt < 8; tt++) {
        size_t node = m0 + mg * 8 + tt;
        #pragma unroll
        for (int p = 0; p < 4; p++) {
            float x, y; unpack2(acc[tt][p], x, y);
            int j = jg * 8 + 2 * p;
            x = fmaxf(x + bias[j], 0.0f);
            y = fmaxf(y + bias[j + 1], 0.0f);
            *reinterpret_cast<float2*>(&out[node * N + j]) = make_float2(x, y);
        }
    }
}

// ---------------- pool + FC ----------------
__global__ void pool_fc_kernel(const float* __restrict__ h,
                               const float* __restrict__ fcW1, const float* __restrict__ fcb1,
                               const float* __restrict__ fcW2, const float* __restrict__ fcb2,
                               float* __restrict__ out) {
    __shared__ float red[256];
    __shared__ float pool[64];
    __shared__ float z1[10];
    int g = blockIdx.x, t = threadIdx.x;
    int f = t & 63, part = t >> 6;
    float s = 0.0f;
    for (int n = part; n < NPG; n += 4)
        s += h[(size_t)(g * NPG + n) * 64 + f];
    red[t] = s;
    __syncthreads();
    if (part == 0)
        pool[f] = (red[f] + red[64 + f] + red[128 + f] + red[192 + f]) * (1.0f / NPG);
    __syncthreads();
    if (t < 10) {
        float z = fcb1[t];
        for (int i = 0; i < 64; i++) z += pool[i] * fcW1[i * 10 + t];
        z1[t] = fmaxf(z, 0.0f);
    }
    __syncthreads();
    if (t < 10) {
        float z = fcb2[t];
        for (int j = 0; j < 10; j++) z += z1[j] * fcW2[j * 10 + t];
        out[g * 10 + t] = z;
    }
}

// ---------------- launch ----------------
extern "C" void kernel_launch(void* const* d_in, const int* in_sizes, int n_in,
                              void* d_out, int out_size) {
    const float* x     = (const float*)d_in[0];
    const int*   ei    = (const int*)d_in[1];
    const float* lam   = (const float*)d_in[3];
    const float* W1 = (const float*)d_in[4];  const float* b1 = (const float*)d_in[5];
    const float* W2 = (const float*)d_in[6];  const float* b2 = (const float*)d_in[7];
    const float* W3 = (const float*)d_in[8];  const float* b3 = (const float*)d_in[9];
    const float* fcW1 = (const float*)d_in[10]; const float* fcb1 = (const float*)d_in[11];
    const float* fcW2 = (const float*)d_in[12]; const float* fcb2 = (const float*)d_in[13];
    float* out = (float*)d_out;

    const int SMEM = 2 * NPG * CF * sizeof(float);  // 65536
    cudaFuncSetAttribute(spmv_kernel<128>, cudaFuncAttributeMaxDynamicSharedMemorySize, SMEM);
    cudaFuncSetAttribute(spmv_kernel<32>,  cudaFuncAttributeMaxDynamicSharedMemorySize, SMEM);
    cudaFuncSetAttribute(spmv_kernel<64>,  cudaFuncAttributeMaxDynamicSharedMemorySize, SMEM);

    float* tx = nullptr; float* ha = nullptr; float* hb = nullptr;
    cudaGetSymbolAddress((void**)&tx, g_tx);
    cudaGetSymbolAddress((void**)&ha, g_ha);
    cudaGetSymbolAddress((void**)&hb, g_hb);

    // counters are zero from static init / previous replay's tail zero_kernel
    deg_kernel<<<NE / 256, 256>>>(ei);                      // 0
    fill_kernel<<<NE / 256, 256>>>(ei, lam);                // 1

    spmv_kernel<128><<<dim3(16, NG), 1024, SMEM>>>(x, lam, tx);   // 2
    gemm_kernel<640, 32, 512><<<NN / 512, 256>>>(tx, W1, b1, ha); // 3 <- ncu captures this

    spmv_kernel<32><<<dim3(4, NG), 1024, SMEM>>>(ha, lam, tx);
    gemm_kernel<160, 64, 256><<<NN / 256, 256>>>(tx, W2, b2, hb);

    spmv_kernel<64><<<dim3(8, NG), 1024, SMEM>>>(hb, lam, tx);
    gemm_kernel<320, 64, 256><<<NN / 256, 256>>>(tx, W3, b3, ha);

    pool_fc_kernel<<<NG, 256>>>(ha, fcW1, fcb1, fcW2, fcb2, out);

    zero_kernel<<<NN / 256, 256>>>();   // tail: reset counters for next replay
}